// round 5
// baseline (speedup 1.0000x reference)
#include <cuda_runtime.h>
#include <cuda_fp16.h>
#include <cstdint>

#define L2E 1.4426950408889634f
#define T2L 2.8853900817779268f
#define NT 384
#define ROWS 192

struct Smem {
    __half W0[16384];   // layer0 Whh (swizzled, prescaled)
    __half W1a[16384];  // layer1 Wih
    __half W1b[16384];  // layer1 Whh
    float wx[512];      // layer0 Wih [256][2] prescaled
    float b0[256], b1[256];
    float fcw[128], fcb[2];
    float obs[ROWS * 16];
};

__device__ __forceinline__ float ex2f(float x) {
    float r; asm("ex2.approx.f32 %0, %1;" : "=f"(r) : "f"(x)); return r;
}
__device__ __forceinline__ float rcpf(float x) {
    float r; asm("rcp.approx.f32 %0, %1;" : "=f"(r) : "f"(x)); return r;
}
__device__ __forceinline__ void mma16(float* d, uint32_t a0, uint32_t a1,
                                      uint32_t a2, uint32_t a3,
                                      uint32_t b0, uint32_t b1) {
    asm volatile(
        "mma.sync.aligned.m16n8k16.row.col.f32.f16.f16.f32 "
        "{%0,%1,%2,%3},{%4,%5,%6,%7},{%8,%9},{%0,%1,%2,%3};"
        : "+f"(d[0]), "+f"(d[1]), "+f"(d[2]), "+f"(d[3])
        : "r"(a0), "r"(a1), "r"(a2), "r"(a3), "r"(b0), "r"(b1));
}
// B-fragment word (half2) at gate-row g, word index w (0..31), XOR-swizzled.
__device__ __forceinline__ uint32_t Bf(const __half* W, int g, int w) {
    return *(const uint32_t*)(W + g * 64 + ((w ^ ((g & 7) << 2)) << 1));
}
__device__ __forceinline__ void loadW(__half* Wt, const float* __restrict__ G) {
    for (int i = threadIdx.x; i < 8192; i += NT) {
        int g = i >> 5, w = i & 31;
        float sc = ((g >> 6) == 2) ? T2L : L2E;
        float2 v = *(const float2*)(G + g * 64 + 2 * w);
        *(__half2*)(Wt + g * 64 + ((w ^ ((g & 7) << 2)) << 1)) =
            __floats2half2_rn(v.x * sc, v.y * sc);
    }
}
__device__ __forceinline__ void loadSmall(Smem* s, const float* Wih0,
                                          const float* Bi0, const float* Bh0,
                                          const float* Bi1, const float* Bh1) {
    for (int g = threadIdx.x; g < 256; g += NT) {
        float sc = ((g >> 6) == 2) ? T2L : L2E;
        s->wx[2 * g] = Wih0[2 * g] * sc;
        s->wx[2 * g + 1] = Wih0[2 * g + 1] * sc;
        s->b0[g] = (Bi0[g] + Bh0[g]) * sc;
        s->b1[g] = (Bi1[g] + Bh1[g]) * sc;
    }
}

// One LSTM layer for this lane's 16-row slice (rows l4 and l4+8 of warp tile).
// hl/hh: this layer's h fragments (in: prev h, out: new h). TWOA adds xl/xh @ W2.
template <bool HASX, bool TWOA, bool FC>
__device__ __forceinline__ void layer(
    const __half* W, const __half* W2, const float* bias, const float* wx,
    const float* fcw, float x0l, float x1l, float x0h, float x1h,
    uint32_t* hl, uint32_t* hh, const uint32_t* xl, const uint32_t* xh,
    float* c, float* sfc, int l4, int lm4)
{
    uint32_t nhl[8], nhh[8];
#pragma unroll
    for (int ut = 0; ut < 8; ut++) {
        float d[4][4];
#pragma unroll
        for (int gt = 0; gt < 4; gt++) {
            d[gt][0] = d[gt][1] = d[gt][2] = d[gt][3] = 0.f;
            int g = gt * 64 + ut * 8 + l4;
#pragma unroll
            for (int kc = 0; kc < 4; kc++) {
                mma16(d[gt], hl[2 * kc], hh[2 * kc], hl[2 * kc + 1], hh[2 * kc + 1],
                      Bf(W, g, kc * 8 + lm4), Bf(W, g, kc * 8 + lm4 + 4));
                if (TWOA)
                    mma16(d[gt], xl[2 * kc], xh[2 * kc], xl[2 * kc + 1], xh[2 * kc + 1],
                          Bf(W2, g, kc * 8 + lm4), Bf(W2, g, kc * 8 + lm4 + 4));
            }
        }
        float hv[4];
#pragma unroll
        for (int e = 0; e < 4; e++) {
            int u = ut * 8 + lm4 * 2 + (e & 1);
            float gi = d[0][e] + bias[u];
            float gf = d[1][e] + bias[64 + u];
            float gg = d[2][e] + bias[128 + u];
            float go = d[3][e] + bias[192 + u];
            if (HASX) {
                float xa = (e < 2) ? x0l : x0h, xb = (e < 2) ? x1l : x1h;
                gi += xa * wx[2 * u] + xb * wx[2 * u + 1];
                gf += xa * wx[2 * (64 + u)] + xb * wx[2 * (64 + u) + 1];
                gg += xa * wx[2 * (128 + u)] + xb * wx[2 * (128 + u) + 1];
                go += xa * wx[2 * (192 + u)] + xb * wx[2 * (192 + u) + 1];
            }
            float ei = ex2f(gi), ef = ex2f(gf), E = ex2f(gg), eo = ex2f(go);
            float cc = c[ut * 4 + e];
            float P = (1.f + ei) * (E + 1.f), Fp = 1.f + ef;
            cc = (ef * cc * P + ei * (E - 1.f) * Fp) * rcpf(Fp * P);
            c[ut * 4 + e] = cc;
            float Ec = ex2f(cc * T2L);
            hv[e] = eo * (Ec - 1.f) * rcpf((1.f + eo) * (Ec + 1.f));
        }
        if (FC) {
            int u0 = ut * 8 + lm4 * 2, u1 = u0 + 1;
            sfc[0] += hv[0] * fcw[u0] + hv[1] * fcw[u1];
            sfc[1] += hv[0] * fcw[64 + u0] + hv[1] * fcw[64 + u1];
            sfc[2] += hv[2] * fcw[u0] + hv[3] * fcw[u1];
            sfc[3] += hv[2] * fcw[64 + u0] + hv[3] * fcw[64 + u1];
        }
        __half2 plo = __floats2half2_rn(hv[0], hv[1]);
        __half2 phi = __floats2half2_rn(hv[2], hv[3]);
        nhl[ut] = *(uint32_t*)&plo;
        nhh[ut] = *(uint32_t*)&phi;
    }
#pragma unroll
    for (int i = 0; i < 8; i++) { hl[i] = nhl[i]; hh[i] = nhh[i]; }
}

__global__ __launch_bounds__(NT, 1)
void SimpleLSTM_49709951484004_kernel(
    const float* __restrict__ obs,
    const float* __restrict__ eWih0, const float* __restrict__ eWhh0,
    const float* __restrict__ eBih0, const float* __restrict__ eBhh0,
    const float* __restrict__ eWih1, const float* __restrict__ eWhh1,
    const float* __restrict__ eBih1, const float* __restrict__ eBhh1,
    const float* __restrict__ dWih0, const float* __restrict__ dWhh0,
    const float* __restrict__ dBih0, const float* __restrict__ dBhh0,
    const float* __restrict__ dWih1, const float* __restrict__ dWhh1,
    const float* __restrict__ dBih1, const float* __restrict__ dBhh1,
    const float* __restrict__ fcW, const float* __restrict__ fcb,
    float* __restrict__ out, int Btot)
{
    extern __shared__ char smraw[];
    Smem* s = (Smem*)smraw;
    const int tid = threadIdx.x;
    const int w = tid >> 5, l = tid & 31, l4 = l >> 2, lm4 = l & 3;
    const int rl = w * 16 + l4;
    const long base = (long)blockIdx.x * ROWS;

    for (int i = tid; i < ROWS * 16; i += NT)
        s->obs[i] = (base + i / 16 < Btot) ? obs[base * 16 + i] : 0.f;
    loadW(s->W0, eWhh0); loadW(s->W1a, eWih1); loadW(s->W1b, eWhh1);
    loadSmall(s, eWih0, eBih0, eBhh0, eBih1, eBhh1);
    if (tid < 128) s->fcw[tid] = fcW[tid];
    if (tid < 2) s->fcb[tid] = fcb[tid];
    __syncthreads();

    uint32_t h0l[8], h0h[8], h1l[8], h1h[8];
    float c0[32], c1[32];
#pragma unroll
    for (int i = 0; i < 8; i++) { h0l[i] = h0h[i] = h1l[i] = h1h[i] = 0u; }
#pragma unroll
    for (int i = 0; i < 32; i++) { c0[i] = 0.f; c1[i] = 0.f; }

    // ---------------- encoder: 8 steps ----------------
#pragma unroll 1
    for (int t = 0; t < 8; t++) {
        float x0l = s->obs[rl * 16 + 2 * t], x1l = s->obs[rl * 16 + 2 * t + 1];
        float x0h = s->obs[(rl + 8) * 16 + 2 * t], x1h = s->obs[(rl + 8) * 16 + 2 * t + 1];
        layer<true, false, false>(s->W0, nullptr, s->b0, s->wx, nullptr,
                                  x0l, x1l, x0h, x1h, h0l, h0h, nullptr, nullptr,
                                  c0, nullptr, l4, lm4);
        layer<false, true, false>(s->W1b, s->W1a, s->b1, nullptr, nullptr,
                                  0.f, 0.f, 0.f, 0.f, h1l, h1h, h0l, h0h,
                                  c1, nullptr, l4, lm4);
    }
    __syncthreads();
    loadW(s->W0, dWhh0); loadW(s->W1a, dWih1); loadW(s->W1b, dWhh1);
    loadSmall(s, dWih0, dBih0, dBhh0, dBih1, dBhh1);
    __syncthreads();

    // ---------------- decoder: 12 steps ----------------
    float x0l = s->obs[rl * 16 + 14], x1l = s->obs[rl * 16 + 15];
    float x0h = s->obs[(rl + 8) * 16 + 14], x1h = s->obs[(rl + 8) * 16 + 15];
#pragma unroll 1
    for (int t = 0; t < 12; t++) {
        layer<true, false, false>(s->W0, nullptr, s->b0, s->wx, nullptr,
                                  x0l, x1l, x0h, x1h, h0l, h0h, nullptr, nullptr,
                                  c0, nullptr, l4, lm4);
        float sfc[4] = {0.f, 0.f, 0.f, 0.f};
        layer<false, true, true>(s->W1b, s->W1a, s->b1, nullptr, s->fcw,
                                 0.f, 0.f, 0.f, 0.f, h1l, h1h, h0l, h0h,
                                 c1, sfc, l4, lm4);
#pragma unroll
        for (int i = 0; i < 4; i++) {
            sfc[i] += __shfl_xor_sync(0xffffffffu, sfc[i], 1);
            sfc[i] += __shfl_xor_sync(0xffffffffu, sfc[i], 2);
        }
        x0l = sfc[0] + s->fcb[0]; x1l = sfc[1] + s->fcb[1];
        x0h = sfc[2] + s->fcb[0]; x1h = sfc[3] + s->fcb[1];
        if (lm4 == 0) {
            long r0 = base + rl, r1 = r0 + 8;
            if (r0 < Btot) { out[r0 * 24 + t * 2] = x0l; out[r0 * 24 + t * 2 + 1] = x1l; }
            if (r1 < Btot) { out[r1 * 24 + t * 2] = x0h; out[r1 * 24 + t * 2 + 1] = x1h; }
        }
    }
}

extern "C" void kernel_launch(void* const* d_in, const int* in_sizes, int n_in,
                              void* d_out, int out_size) {
    int Btot = in_sizes[0] / 16;
    int grid = (Btot + ROWS - 1) / ROWS;
    cudaFuncSetAttribute(SimpleLSTM_49709951484004_kernel,
                         cudaFuncAttributeMaxDynamicSharedMemorySize,
                         (int)sizeof(Smem));
    SimpleLSTM_49709951484004_kernel<<<grid, NT, sizeof(Smem)>>>(
        (const float*)d_in[0], (const float*)d_in[1], (const float*)d_in[2],
        (const float*)d_in[3], (const float*)d_in[4], (const float*)d_in[5],
        (const float*)d_in[6], (const float*)d_in[7], (const float*)d_in[8],
        (const float*)d_in[9], (const float*)d_in[10], (const float*)d_in[11],
        (const float*)d_in[12], (const float*)d_in[13], (const float*)d_in[14],
        (const float*)d_in[15], (const float*)d_in[16], (const float*)d_in[17],
        (const float*)d_in[18], (float*)d_out, Btot);
}

// round 6
// speedup vs baseline: 1.0273x; 1.0273x over previous
#include <cuda_runtime.h>
#include <cuda_fp16.h>
#include <cstdint>

#define L2E 1.4426950408889634f
#define T2L 2.8853900817779268f
#define NT 384
#define ROWS 192

struct Smem {
    __half W0[16384];   // layer0 Whh [g][k], 16B-chunk swizzled, prescaled
    __half W1a[16384];  // layer1 Wih
    __half W1b[16384];  // layer1 Whh
    float wx[512];      // layer0 Wih [256][2] prescaled
    float b0[256], b1[256];
    float fcw[128], fcb[2];
    float obs[ROWS * 16];
};

__device__ __forceinline__ float ex2f(float x) {
    float r; asm("ex2.approx.f32 %0, %1;" : "=f"(r) : "f"(x)); return r;
}
__device__ __forceinline__ float rcpf(float x) {
    float r; asm("rcp.approx.f32 %0, %1;" : "=f"(r) : "f"(x)); return r;
}
__device__ __forceinline__ uint32_t smem_u32(const void* p) {
    uint32_t a;
    asm("{ .reg .u64 t; cvta.to.shared.u64 t, %1; cvt.u32.u64 %0, t; }"
        : "=r"(a) : "l"(p));
    return a;
}
__device__ __forceinline__ void ldm4(uint32_t* f, uint32_t addr) {
    asm volatile("ldmatrix.sync.aligned.m8n8.x4.shared.b16 {%0,%1,%2,%3}, [%4];"
        : "=r"(f[0]), "=r"(f[1]), "=r"(f[2]), "=r"(f[3]) : "r"(addr));
}
__device__ __forceinline__ void mma16(float* d, uint32_t a0, uint32_t a1,
                                      uint32_t a2, uint32_t a3,
                                      uint32_t b0, uint32_t b1) {
    asm volatile(
        "mma.sync.aligned.m16n8k16.row.col.f32.f16.f16.f32 "
        "{%0,%1,%2,%3},{%4,%5,%6,%7},{%8,%9},{%0,%1,%2,%3};"
        : "+f"(d[0]), "+f"(d[1]), "+f"(d[2]), "+f"(d[3])
        : "r"(a0), "r"(a1), "r"(a2), "r"(a3), "r"(b0), "r"(b1));
}

// W[g][k] -> smem, prescaled; 16B chunk c of row g stored at chunk c ^ (g&7).
__device__ __forceinline__ void loadW(__half* Wt, const float* __restrict__ G) {
    for (int i = threadIdx.x; i < 8192; i += NT) {
        int g = i >> 5, w = i & 31;                 // w: half2 word 0..31
        float sc = ((g >> 6) == 2) ? T2L : L2E;
        float2 v = *(const float2*)(G + g * 64 + 2 * w);
        int pos = (w >> 2) ^ (g & 7);               // swizzled 16B chunk
        *(__half2*)(Wt + g * 64 + pos * 8 + (w & 3) * 2) =
            __floats2half2_rn(v.x * sc, v.y * sc);
    }
}
__device__ __forceinline__ void loadSmall(Smem* s, const float* Wih0,
                                          const float* Bi0, const float* Bh0,
                                          const float* Bi1, const float* Bh1) {
    for (int g = threadIdx.x; g < 256; g += NT) {
        float sc = ((g >> 6) == 2) ? T2L : L2E;
        s->wx[2 * g] = Wih0[2 * g] * sc;
        s->wx[2 * g + 1] = Wih0[2 * g + 1] * sc;
        s->b0[g] = (Bi0[g] + Bh0[g]) * sc;
        s->b1[g] = (Bi1[g] + Bh1[g]) * sc;
    }
}

// One LSTM layer for this lane's 16-row slice. hl/hh updated in place.
// TWOA adds xl/xh @ W2 (matrix at smem addr wB).
template <bool HASX, bool TWOA, bool FC>
__device__ __forceinline__ void layer(
    uint32_t wA, uint32_t wB, const float* bias, const float* wx,
    const float* fcw, float x0l, float x1l, float x0h, float x1h,
    uint32_t* hl, uint32_t* hh, const uint32_t* xl, const uint32_t* xh,
    float* c, float* sfc, int lm4, uint32_t lmoff)
{
    uint32_t nhl[8], nhh[8];
#pragma unroll
    for (int ut = 0; ut < 8; ut++) {
        float d[4][4];
#pragma unroll
        for (int gt = 0; gt < 4; gt++) {
            uint32_t a0 = wA + (uint32_t)(gt * 8192 + ut * 1024) + lmoff;
            uint32_t fA[8];
            ldm4(fA, a0);
            ldm4(fA + 4, a0 ^ 64u);
            d[gt][0] = d[gt][1] = d[gt][2] = d[gt][3] = 0.f;
#pragma unroll
            for (int kc = 0; kc < 4; kc++)
                mma16(d[gt], hl[2 * kc], hh[2 * kc], hl[2 * kc + 1], hh[2 * kc + 1],
                      fA[2 * kc], fA[2 * kc + 1]);
            if (TWOA) {
                uint32_t b0a = wB + (uint32_t)(gt * 8192 + ut * 1024) + lmoff;
                uint32_t fB[8];
                ldm4(fB, b0a);
                ldm4(fB + 4, b0a ^ 64u);
#pragma unroll
                for (int kc = 0; kc < 4; kc++)
                    mma16(d[gt], xl[2 * kc], xh[2 * kc], xl[2 * kc + 1], xh[2 * kc + 1],
                          fB[2 * kc], fB[2 * kc + 1]);
            }
        }
        const int u0 = ut * 8 + lm4 * 2;
        float2 bi = *(const float2*)(bias + u0);
        float2 bf = *(const float2*)(bias + 64 + u0);
        float2 bg = *(const float2*)(bias + 128 + u0);
        float2 bo = *(const float2*)(bias + 192 + u0);
        float4 wi, wf, wg, wo;
        if (HASX) {
            wi = *(const float4*)(wx + 2 * u0);
            wf = *(const float4*)(wx + 2 * (64 + u0));
            wg = *(const float4*)(wx + 2 * (128 + u0));
            wo = *(const float4*)(wx + 2 * (192 + u0));
        }
        float2 f0v, f1v;
        if (FC) {
            f0v = *(const float2*)(fcw + u0);
            f1v = *(const float2*)(fcw + 64 + u0);
        }
        float hv[4];
#pragma unroll
        for (int e = 0; e < 4; e++) {
            const int o = e & 1;
            float gi = d[0][e] + (o ? bi.y : bi.x);
            float gf = d[1][e] + (o ? bf.y : bf.x);
            float gg = d[2][e] + (o ? bg.y : bg.x);
            float go = d[3][e] + (o ? bo.y : bo.x);
            if (HASX) {
                float xa = (e < 2) ? x0l : x0h, xb = (e < 2) ? x1l : x1h;
                gi += xa * (o ? wi.z : wi.x) + xb * (o ? wi.w : wi.y);
                gf += xa * (o ? wf.z : wf.x) + xb * (o ? wf.w : wf.y);
                gg += xa * (o ? wg.z : wg.x) + xb * (o ? wg.w : wg.y);
                go += xa * (o ? wo.z : wo.x) + xb * (o ? wo.w : wo.y);
            }
            float ei = ex2f(gi), ef = ex2f(gf), E = ex2f(gg), eo = ex2f(go);
            float cc = c[ut * 4 + e];
            float P = (1.f + ei) * (E + 1.f), Fp = 1.f + ef;
            cc = (ef * cc * P + ei * (E - 1.f) * Fp) * rcpf(Fp * P);
            c[ut * 4 + e] = cc;
            float Ec = ex2f(cc * T2L);
            hv[e] = eo * (Ec - 1.f) * rcpf((1.f + eo) * (Ec + 1.f));
        }
        if (FC) {
            sfc[0] += hv[0] * f0v.x + hv[1] * f0v.y;
            sfc[1] += hv[0] * f1v.x + hv[1] * f1v.y;
            sfc[2] += hv[2] * f0v.x + hv[3] * f0v.y;
            sfc[3] += hv[2] * f1v.x + hv[3] * f1v.y;
        }
        __half2 plo = __floats2half2_rn(hv[0], hv[1]);
        __half2 phi = __floats2half2_rn(hv[2], hv[3]);
        nhl[ut] = *(uint32_t*)&plo;
        nhh[ut] = *(uint32_t*)&phi;
    }
#pragma unroll
    for (int i = 0; i < 8; i++) { hl[i] = nhl[i]; hh[i] = nhh[i]; }
}

__global__ __launch_bounds__(NT, 1)
void SimpleLSTM_49709951484004_kernel(
    const float* __restrict__ obs,
    const float* __restrict__ eWih0, const float* __restrict__ eWhh0,
    const float* __restrict__ eBih0, const float* __restrict__ eBhh0,
    const float* __restrict__ eWih1, const float* __restrict__ eWhh1,
    const float* __restrict__ eBih1, const float* __restrict__ eBhh1,
    const float* __restrict__ dWih0, const float* __restrict__ dWhh0,
    const float* __restrict__ dBih0, const float* __restrict__ dBhh0,
    const float* __restrict__ dWih1, const float* __restrict__ dWhh1,
    const float* __restrict__ dBih1, const float* __restrict__ dBhh1,
    const float* __restrict__ fcW, const float* __restrict__ fcb,
    float* __restrict__ out, int Btot)
{
    extern __shared__ char smraw[];
    Smem* s = (Smem*)smraw;
    const int tid = threadIdx.x;
    const int w = tid >> 5, l = tid & 31, l4 = l >> 2, lm4 = l & 3;
    const int rl = w * 16 + l4;
    const long base = (long)blockIdx.x * ROWS;
    // ldmatrix per-lane address offset: lane = 8*t + j supplies row j of tile t
    const int j = l & 7, tt = l >> 3;
    const uint32_t lmoff = (uint32_t)(j * 128 + (((tt ^ j) & 7) << 4));

    for (int i = tid; i < ROWS * 16; i += NT)
        s->obs[i] = (base + i / 16 < Btot) ? obs[base * 16 + i] : 0.f;
    loadW(s->W0, eWhh0); loadW(s->W1a, eWih1); loadW(s->W1b, eWhh1);
    loadSmall(s, eWih0, eBih0, eBhh0, eBih1, eBhh1);
    if (tid < 128) s->fcw[tid] = fcW[tid];
    if (tid < 2) s->fcb[tid] = fcb[tid];
    __syncthreads();

    const uint32_t uW0 = smem_u32(s->W0);
    const uint32_t uW1a = smem_u32(s->W1a);
    const uint32_t uW1b = smem_u32(s->W1b);

    uint32_t h0l[8], h0h[8], h1l[8], h1h[8];
    float c0[32], c1[32];
#pragma unroll
    for (int i = 0; i < 8; i++) { h0l[i] = h0h[i] = h1l[i] = h1h[i] = 0u; }
#pragma unroll
    for (int i = 0; i < 32; i++) { c0[i] = 0.f; c1[i] = 0.f; }

    // ---------------- encoder: 8 steps ----------------
#pragma unroll 1
    for (int t = 0; t < 8; t++) {
        float x0l = s->obs[rl * 16 + 2 * t], x1l = s->obs[rl * 16 + 2 * t + 1];
        float x0h = s->obs[(rl + 8) * 16 + 2 * t], x1h = s->obs[(rl + 8) * 16 + 2 * t + 1];
        layer<true, false, false>(uW0, 0u, s->b0, s->wx, nullptr,
                                  x0l, x1l, x0h, x1h, h0l, h0h, nullptr, nullptr,
                                  c0, nullptr, lm4, lmoff);
        layer<false, true, false>(uW1b, uW1a, s->b1, nullptr, nullptr,
                                  0.f, 0.f, 0.f, 0.f, h1l, h1h, h0l, h0h,
                                  c1, nullptr, lm4, lmoff);
    }
    __syncthreads();
    loadW(s->W0, dWhh0); loadW(s->W1a, dWih1); loadW(s->W1b, dWhh1);
    loadSmall(s, dWih0, dBih0, dBhh0, dBih1, dBhh1);
    __syncthreads();

    // ---------------- decoder: 12 steps ----------------
    float x0l = s->obs[rl * 16 + 14], x1l = s->obs[rl * 16 + 15];
    float x0h = s->obs[(rl + 8) * 16 + 14], x1h = s->obs[(rl + 8) * 16 + 15];
#pragma unroll 1
    for (int t = 0; t < 12; t++) {
        layer<true, false, false>(uW0, 0u, s->b0, s->wx, nullptr,
                                  x0l, x1l, x0h, x1h, h0l, h0h, nullptr, nullptr,
                                  c0, nullptr, lm4, lmoff);
        float sfc[4] = {0.f, 0.f, 0.f, 0.f};
        layer<false, true, true>(uW1b, uW1a, s->b1, nullptr, s->fcw,
                                 0.f, 0.f, 0.f, 0.f, h1l, h1h, h0l, h0h,
                                 c1, sfc, lm4, lmoff);
#pragma unroll
        for (int i = 0; i < 4; i++) {
            sfc[i] += __shfl_xor_sync(0xffffffffu, sfc[i], 1);
            sfc[i] += __shfl_xor_sync(0xffffffffu, sfc[i], 2);
        }
        x0l = sfc[0] + s->fcb[0]; x1l = sfc[1] + s->fcb[1];
        x0h = sfc[2] + s->fcb[0]; x1h = sfc[3] + s->fcb[1];
        if (lm4 == 0) {
            long r0 = base + rl, r1 = r0 + 8;
            if (r0 < Btot) { out[r0 * 24 + t * 2] = x0l; out[r0 * 24 + t * 2 + 1] = x1l; }
            if (r1 < Btot) { out[r1 * 24 + t * 2] = x0h; out[r1 * 24 + t * 2 + 1] = x1h; }
        }
    }
}

extern "C" void kernel_launch(void* const* d_in, const int* in_sizes, int n_in,
                              void* d_out, int out_size) {
    int Btot = in_sizes[0] / 16;
    int grid = (Btot + ROWS - 1) / ROWS;
    cudaFuncSetAttribute(SimpleLSTM_49709951484004_kernel,
                         cudaFuncAttributeMaxDynamicSharedMemorySize,
                         (int)sizeof(Smem));
    SimpleLSTM_49709951484004_kernel<<<grid, NT, sizeof(Smem)>>>(
        (const float*)d_in[0], (const float*)d_in[1], (const float*)d_in[2],
        (const float*)d_in[3], (const float*)d_in[4], (const float*)d_in[5],
        (const float*)d_in[6], (const float*)d_in[7], (const float*)d_in[8],
        (const float*)d_in[9], (const float*)d_in[10], (const float*)d_in[11],
        (const float*)d_in[12], (const float*)d_in[13], (const float*)d_in[14],
        (const float*)d_in[15], (const float*)d_in[16], (const float*)d_in[17],
        (const float*)d_in[18], (float*)d_out, Btot);
}

// round 8
// speedup vs baseline: 1.3957x; 1.3586x over previous
#include <cuda_runtime.h>
#include <cuda_fp16.h>
#include <cstdint>

#define NT 384
#define ROWS 192

struct Smem {
    __half W[6][16384];   // eWhh0,eWih1,eWhh1,dWhh0,dWih1,dWhh1 (swizzled, prescaled)
    float wxe[512], wxd[512];   // layer0 Wih [256][2] prescaled
    float b0e[256], b1e[256], b0d[256], b1d[256];
    float fcw[128], fcb[2];
    float obs[ROWS * 16];
};

__device__ __forceinline__ float tanhg(float x) {
    float r; asm("tanh.approx.f32 %0, %1;" : "=f"(r) : "f"(x)); return r;
}
__device__ __forceinline__ uint32_t smem_u32(const void* p) {
    uint32_t a;
    asm("{ .reg .u64 t; cvta.to.shared.u64 t, %1; cvt.u32.u64 %0, t; }"
        : "=r"(a) : "l"(p));
    return a;
}
__device__ __forceinline__ void ldm4(uint32_t* f, uint32_t addr) {
    asm volatile("ldmatrix.sync.aligned.m8n8.x4.shared.b16 {%0,%1,%2,%3}, [%4];"
        : "=r"(f[0]), "=r"(f[1]), "=r"(f[2]), "=r"(f[3]) : "r"(addr));
}
__device__ __forceinline__ void mma16(float* d, uint32_t a0, uint32_t a1,
                                      uint32_t a2, uint32_t a3,
                                      uint32_t b0, uint32_t b1) {
    asm volatile(
        "mma.sync.aligned.m16n8k16.row.col.f32.f16.f16.f32 "
        "{%0,%1,%2,%3},{%4,%5,%6,%7},{%8,%9},{%0,%1,%2,%3};"
        : "+f"(d[0]), "+f"(d[1]), "+f"(d[2]), "+f"(d[3])
        : "r"(a0), "r"(a1), "r"(a2), "r"(a3), "r"(b0), "r"(b1));
}

// W[g][k] -> smem, prescaled (0.5 for i/f/o gates, 1.0 for g gate);
// 16B chunk c of row g stored at chunk c ^ (g&7).
__device__ __forceinline__ void loadW(__half* Wt, const float* __restrict__ G) {
    for (int i = threadIdx.x; i < 8192; i += NT) {
        int g = i >> 5, w = i & 31;
        float sc = ((g >> 6) == 2) ? 1.0f : 0.5f;
        float2 v = *(const float2*)(G + g * 64 + 2 * w);
        int pos = (w >> 2) ^ (g & 7);
        *(__half2*)(Wt + g * 64 + pos * 8 + (w & 3) * 2) =
            __floats2half2_rn(v.x * sc, v.y * sc);
    }
}
__device__ __forceinline__ void loadSmall(float* wx, float* b0, float* b1,
                                          const float* Wih0,
                                          const float* Bi0, const float* Bh0,
                                          const float* Bi1, const float* Bh1) {
    for (int g = threadIdx.x; g < 256; g += NT) {
        float sc = ((g >> 6) == 2) ? 1.0f : 0.5f;
        wx[2 * g] = Wih0[2 * g] * sc;
        wx[2 * g + 1] = Wih0[2 * g + 1] * sc;
        b0[g] = (Bi0[g] + Bh0[g]) * sc;
        b1[g] = (Bi1[g] + Bh1[g]) * sc;
    }
}

// One LSTM layer for this lane's 16-row slice. hl/hh updated in place.
// TWOA adds xl/xh @ W2 (matrix at smem addr wB).
template <bool HASX, bool TWOA, bool FC>
__device__ __forceinline__ void layer(
    uint32_t wA, uint32_t wB, const float* bias, const float* wx,
    const float* fcw, float x0l, float x1l, float x0h, float x1h,
    uint32_t* hl, uint32_t* hh, const uint32_t* xl, const uint32_t* xh,
    float* c, float* sfc, int lm4, uint32_t lmoff)
{
    uint32_t nhl[8], nhh[8];
#pragma unroll
    for (int ut = 0; ut < 8; ut++) {
        float d[4][4];
#pragma unroll
        for (int gt = 0; gt < 4; gt++)
            d[gt][0] = d[gt][1] = d[gt][2] = d[gt][3] = 0.f;
        {   // A-matrix: hoist all fragments, interleave 4 accumulator chains
            uint32_t f[4][8];
#pragma unroll
            for (int gt = 0; gt < 4; gt++) {
                uint32_t a0 = wA + (uint32_t)(gt * 8192 + ut * 1024) + lmoff;
                ldm4(f[gt], a0);
                ldm4(f[gt] + 4, a0 ^ 64u);
            }
#pragma unroll
            for (int kc = 0; kc < 4; kc++)
#pragma unroll
                for (int gt = 0; gt < 4; gt++)
                    mma16(d[gt], hl[2 * kc], hh[2 * kc], hl[2 * kc + 1], hh[2 * kc + 1],
                          f[gt][2 * kc], f[gt][2 * kc + 1]);
        }
        if (TWOA) {
            uint32_t f[4][8];
#pragma unroll
            for (int gt = 0; gt < 4; gt++) {
                uint32_t a0 = wB + (uint32_t)(gt * 8192 + ut * 1024) + lmoff;
                ldm4(f[gt], a0);
                ldm4(f[gt] + 4, a0 ^ 64u);
            }
#pragma unroll
            for (int kc = 0; kc < 4; kc++)
#pragma unroll
                for (int gt = 0; gt < 4; gt++)
                    mma16(d[gt], xl[2 * kc], xh[2 * kc], xl[2 * kc + 1], xh[2 * kc + 1],
                          f[gt][2 * kc], f[gt][2 * kc + 1]);
        }
        const int u0 = ut * 8 + lm4 * 2;
        float2 bi = *(const float2*)(bias + u0);
        float2 bf = *(const float2*)(bias + 64 + u0);
        float2 bg = *(const float2*)(bias + 128 + u0);
        float2 bo = *(const float2*)(bias + 192 + u0);
        float4 wi, wf, wg, wo;
        if (HASX) {
            wi = *(const float4*)(wx + 2 * u0);
            wf = *(const float4*)(wx + 2 * (64 + u0));
            wg = *(const float4*)(wx + 2 * (128 + u0));
            wo = *(const float4*)(wx + 2 * (192 + u0));
        }
        float2 f0v, f1v;
        if (FC) {
            f0v = *(const float2*)(fcw + u0);
            f1v = *(const float2*)(fcw + 64 + u0);
        }
        float hv[4];
#pragma unroll
        for (int e = 0; e < 4; e++) {
            const int o = e & 1;
            float gi = d[0][e] + (o ? bi.y : bi.x);
            float gf = d[1][e] + (o ? bf.y : bf.x);
            float gg = d[2][e] + (o ? bg.y : bg.x);
            float go = d[3][e] + (o ? bo.y : bo.x);
            if (HASX) {
                float xa = (e < 2) ? x0l : x0h, xb = (e < 2) ? x1l : x1h;
                gi += xa * (o ? wi.z : wi.x) + xb * (o ? wi.w : wi.y);
                gf += xa * (o ? wf.z : wf.x) + xb * (o ? wf.w : wf.y);
                gg += xa * (o ? wg.z : wg.x) + xb * (o ? wg.w : wg.y);
                go += xa * (o ? wo.z : wo.x) + xb * (o ? wo.w : wo.y);
            }
            // sigma(x)=0.5*tanh(x/2)+0.5, 0.5 prescaled into W/b for i,f,o
            float ti = tanhg(gi), tf_ = tanhg(gf), tg = tanhg(gg), to = tanhg(go);
            float si = fmaf(0.5f, ti, 0.5f);
            float sf = fmaf(0.5f, tf_, 0.5f);
            float so = fmaf(0.5f, to, 0.5f);
            float cc = c[ut * 4 + e];
            cc = fmaf(si, tg, sf * cc);
            c[ut * 4 + e] = cc;
            hv[e] = so * tanhg(cc);
        }
        if (FC) {
            sfc[0] += hv[0] * f0v.x + hv[1] * f0v.y;
            sfc[1] += hv[0] * f1v.x + hv[1] * f1v.y;
            sfc[2] += hv[2] * f0v.x + hv[3] * f0v.y;
            sfc[3] += hv[2] * f1v.x + hv[3] * f1v.y;
        }
        __half2 plo = __floats2half2_rn(hv[0], hv[1]);
        __half2 phi = __floats2half2_rn(hv[2], hv[3]);
        nhl[ut] = *(uint32_t*)&plo;
        nhh[ut] = *(uint32_t*)&phi;
    }
#pragma unroll
    for (int i = 0; i < 8; i++) { hl[i] = nhl[i]; hh[i] = nhh[i]; }
}

__global__ __launch_bounds__(NT, 1)
void SimpleLSTM_49709951484004_kernel(
    const float* __restrict__ obs,
    const float* __restrict__ eWih0, const float* __restrict__ eWhh0,
    const float* __restrict__ eBih0, const float* __restrict__ eBhh0,
    const float* __restrict__ eWih1, const float* __restrict__ eWhh1,
    const float* __restrict__ eBih1, const float* __restrict__ eBhh1,
    const float* __restrict__ dWih0, const float* __restrict__ dWhh0,
    const float* __restrict__ dBih0, const float* __restrict__ dBhh0,
    const float* __restrict__ dWih1, const float* __restrict__ dWhh1,
    const float* __restrict__ dBih1, const float* __restrict__ dBhh1,
    const float* __restrict__ fcW, const float* __restrict__ fcb,
    float* __restrict__ out, int Btot)
{
    extern __shared__ char smraw[];
    Smem* s = (Smem*)smraw;
    const int tid = threadIdx.x;
    const int w = tid >> 5, l = tid & 31, l4 = l >> 2, lm4 = l & 3;
    const int rl = w * 16 + l4;
    const long base = (long)blockIdx.x * ROWS;
    const int j = l & 7, tt = l >> 3;
    const uint32_t lmoff = (uint32_t)(j * 128 + (((tt ^ j) & 7) << 4));

    for (int i = tid; i < ROWS * 16; i += NT)
        s->obs[i] = (base + i / 16 < Btot) ? obs[base * 16 + i] : 0.f;
    loadW(s->W[0], eWhh0); loadW(s->W[1], eWih1); loadW(s->W[2], eWhh1);
    loadW(s->W[3], dWhh0); loadW(s->W[4], dWih1); loadW(s->W[5], dWhh1);
    loadSmall(s->wxe, s->b0e, s->b1e, eWih0, eBih0, eBhh0, eBih1, eBhh1);
    loadSmall(s->wxd, s->b0d, s->b1d, dWih0, dBih0, dBhh0, dBih1, dBhh1);
    if (tid < 128) s->fcw[tid] = fcW[tid];
    if (tid < 2) s->fcb[tid] = fcb[tid];
    __syncthreads();

    const uint32_t uW = smem_u32(s->W[0]);

    uint32_t h0l[8], h0h[8], h1l[8], h1h[8];
    float c0[32], c1[32];
#pragma unroll
    for (int i = 0; i < 8; i++) { h0l[i] = h0h[i] = h1l[i] = h1h[i] = 0u; }
#pragma unroll
    for (int i = 0; i < 32; i++) { c0[i] = 0.f; c1[i] = 0.f; }

    // ---------------- encoder: 8 steps ----------------
#pragma unroll 1
    for (int t = 0; t < 8; t++) {
        float x0l = s->obs[rl * 16 + 2 * t], x1l = s->obs[rl * 16 + 2 * t + 1];
        float x0h = s->obs[(rl + 8) * 16 + 2 * t], x1h = s->obs[(rl + 8) * 16 + 2 * t + 1];
        layer<true, false, false>(uW, 0u, s->b0e, s->wxe, nullptr,
                                  x0l, x1l, x0h, x1h, h0l, h0h, nullptr, nullptr,
                                  c0, nullptr, lm4, lmoff);
        layer<false, true, false>(uW + 2 * 32768u, uW + 1 * 32768u, s->b1e, nullptr,
                                  nullptr, 0.f, 0.f, 0.f, 0.f, h1l, h1h, h0l, h0h,
                                  c1, nullptr, lm4, lmoff);
    }

    // ---------------- decoder: 12 steps ----------------
    float x0l = s->obs[rl * 16 + 14], x1l = s->obs[rl * 16 + 15];
    float x0h = s->obs[(rl + 8) * 16 + 14], x1h = s->obs[(rl + 8) * 16 + 15];
#pragma unroll 1
    for (int t = 0; t < 12; t++) {
        layer<true, false, false>(uW + 3 * 32768u, 0u, s->b0d, s->wxd, nullptr,
                                  x0l, x1l, x0h, x1h, h0l, h0h, nullptr, nullptr,
                                  c0, nullptr, lm4, lmoff);
        float sfc[4] = {0.f, 0.f, 0.f, 0.f};
        layer<false, true, true>(uW + 5 * 32768u, uW + 4 * 32768u, s->b1d, nullptr,
                                 s->fcw, 0.f, 0.f, 0.f, 0.f, h1l, h1h, h0l, h0h,
                                 c1, sfc, lm4, lmoff);
#pragma unroll
        for (int i = 0; i < 4; i++) {
            sfc[i] += __shfl_xor_sync(0xffffffffu, sfc[i], 1);
            sfc[i] += __shfl_xor_sync(0xffffffffu, sfc[i], 2);
        }
        x0l = sfc[0] + s->fcb[0]; x1l = sfc[1] + s->fcb[1];
        x0h = sfc[2] + s->fcb[0]; x1h = sfc[3] + s->fcb[1];
        if (lm4 == 0) {
            long r0 = base + rl, r1 = r0 + 8;
            if (r0 < Btot) { out[r0 * 24 + t * 2] = x0l; out[r0 * 24 + t * 2 + 1] = x1l; }
            if (r1 < Btot) { out[r1 * 24 + t * 2] = x0h; out[r1 * 24 + t * 2 + 1] = x1h; }
        }
    }
}

extern "C" void kernel_launch(void* const* d_in, const int* in_sizes, int n_in,
                              void* d_out, int out_size) {
    int Btot = in_sizes[0] / 16;
    int grid = (Btot + ROWS - 1) / ROWS;
    cudaFuncSetAttribute(SimpleLSTM_49709951484004_kernel,
                         cudaFuncAttributeMaxDynamicSharedMemorySize,
                         (int)sizeof(Smem));
    SimpleLSTM_49709951484004_kernel<<<grid, NT, sizeof(Smem)>>>(
        (const float*)d_in[0], (const float*)d_in[1], (const float*)d_in[2],
        (const float*)d_in[3], (const float*)d_in[4], (const float*)d_in[5],
        (const float*)d_in[6], (const float*)d_in[7], (const float*)d_in[8],
        (const float*)d_in[9], (const float*)d_in[10], (const float*)d_in[11],
        (const float*)d_in[12], (const float*)d_in[13], (const float*)d_in[14],
        (const float*)d_in[15], (const float*)d_in[16], (const float*)d_in[17],
        (const float*)d_in[18], (float*)d_out, Btot);
}

// round 9
// speedup vs baseline: 1.4256x; 1.0214x over previous
#include <cuda_runtime.h>
#include <cuda_fp16.h>
#include <cstdint>

#define NT 256
#define ROWS 128

struct Smem {
    __half W[6][16384];   // eWhh0,eWih1,eWhh1,dWhh0,dWih1,dWhh1 (swizzled, prescaled)
    float wxe[512], wxd[512];   // layer0 Wih [256][2] prescaled
    float b0e[256], b1e[256], b0d[256], b1d[256];
    float fcw[128], fcb[2];
    float obs[ROWS * 16];
};

__device__ __forceinline__ float tanhg(float x) {
    float r; asm("tanh.approx.f32 %0, %1;" : "=f"(r) : "f"(x)); return r;
}
__device__ __forceinline__ uint32_t smem_u32(const void* p) {
    uint32_t a;
    asm("{ .reg .u64 t; cvta.to.shared.u64 t, %1; cvt.u32.u64 %0, t; }"
        : "=r"(a) : "l"(p));
    return a;
}
__device__ __forceinline__ void ldm4(uint32_t* f, uint32_t addr) {
    asm volatile("ldmatrix.sync.aligned.m8n8.x4.shared.b16 {%0,%1,%2,%3}, [%4];"
        : "=r"(f[0]), "=r"(f[1]), "=r"(f[2]), "=r"(f[3]) : "r"(addr));
}
__device__ __forceinline__ void mma16(float* d, uint32_t a0, uint32_t a1,
                                      uint32_t a2, uint32_t a3,
                                      uint32_t b0, uint32_t b1) {
    asm volatile(
        "mma.sync.aligned.m16n8k16.row.col.f32.f16.f16.f32 "
        "{%0,%1,%2,%3},{%4,%5,%6,%7},{%8,%9},{%0,%1,%2,%3};"
        : "+f"(d[0]), "+f"(d[1]), "+f"(d[2]), "+f"(d[3])
        : "r"(a0), "r"(a1), "r"(a2), "r"(a3), "r"(b0), "r"(b1));
}

// W[g][k] -> smem, prescaled (0.5 for i/f/o gates, 1.0 for g gate);
// 16B chunk c of row g stored at chunk c ^ (g&7).
__device__ __forceinline__ void loadW(__half* Wt, const float* __restrict__ G) {
    for (int i = threadIdx.x; i < 8192; i += NT) {
        int g = i >> 5, w = i & 31;
        float sc = ((g >> 6) == 2) ? 1.0f : 0.5f;
        float2 v = *(const float2*)(G + g * 64 + 2 * w);
        int pos = (w >> 2) ^ (g & 7);
        *(__half2*)(Wt + g * 64 + pos * 8 + (w & 3) * 2) =
            __floats2half2_rn(v.x * sc, v.y * sc);
    }
}
__device__ __forceinline__ void loadSmall(float* wx, float* b0, float* b1,
                                          const float* Wih0,
                                          const float* Bi0, const float* Bh0,
                                          const float* Bi1, const float* Bh1) {
    for (int g = threadIdx.x; g < 256; g += NT) {
        float sc = ((g >> 6) == 2) ? 1.0f : 0.5f;
        wx[2 * g] = Wih0[2 * g] * sc;
        wx[2 * g + 1] = Wih0[2 * g + 1] * sc;
        b0[g] = (Bi0[g] + Bh0[g]) * sc;
        b1[g] = (Bi1[g] + Bh1[g]) * sc;
    }
}

// One LSTM layer for this lane's 16-row slice. hl/hh updated in place.
// TWOA adds xl/xh @ W2 (matrix at smem addr wB). Bias pre-loaded into accum.
template <bool HASX, bool TWOA, bool FC>
__device__ __forceinline__ void layer(
    uint32_t wA, uint32_t wB, const float* bias, const float* wx,
    const float* fcw, float x0l, float x1l, float x0h, float x1h,
    uint32_t* hl, uint32_t* hh, const uint32_t* xl, const uint32_t* xh,
    float* c, float* sfc, int lm4, uint32_t lmoff)
{
    uint32_t nhl[8], nhh[8];
#pragma unroll
    for (int ut = 0; ut < 8; ut++) {
        const int u0 = ut * 8 + lm4 * 2;
        float d[4][4];
        // accumulators start at the (prescaled) bias
#pragma unroll
        for (int gt = 0; gt < 4; gt++) {
            float2 bb = *(const float2*)(bias + gt * 64 + u0);
            d[gt][0] = bb.x; d[gt][1] = bb.y;
            d[gt][2] = bb.x; d[gt][3] = bb.y;
        }
        // hoist ALL fragment loads (A and, if TWOA, B) before the MMA blocks
        uint32_t fA[4][8];
#pragma unroll
        for (int gt = 0; gt < 4; gt++) {
            uint32_t a0 = wA + (uint32_t)(gt * 8192 + ut * 1024) + lmoff;
            ldm4(fA[gt], a0);
            ldm4(fA[gt] + 4, a0 ^ 64u);
        }
        if (TWOA) {
            uint32_t fB[4][8];
#pragma unroll
            for (int gt = 0; gt < 4; gt++) {
                uint32_t a0 = wB + (uint32_t)(gt * 8192 + ut * 1024) + lmoff;
                ldm4(fB[gt], a0);
                ldm4(fB[gt] + 4, a0 ^ 64u);
            }
#pragma unroll
            for (int kc = 0; kc < 4; kc++)
#pragma unroll
                for (int gt = 0; gt < 4; gt++)
                    mma16(d[gt], hl[2 * kc], hh[2 * kc], hl[2 * kc + 1], hh[2 * kc + 1],
                          fA[gt][2 * kc], fA[gt][2 * kc + 1]);
#pragma unroll
            for (int kc = 0; kc < 4; kc++)
#pragma unroll
                for (int gt = 0; gt < 4; gt++)
                    mma16(d[gt], xl[2 * kc], xh[2 * kc], xl[2 * kc + 1], xh[2 * kc + 1],
                          fB[gt][2 * kc], fB[gt][2 * kc + 1]);
        } else {
#pragma unroll
            for (int kc = 0; kc < 4; kc++)
#pragma unroll
                for (int gt = 0; gt < 4; gt++)
                    mma16(d[gt], hl[2 * kc], hh[2 * kc], hl[2 * kc + 1], hh[2 * kc + 1],
                          fA[gt][2 * kc], fA[gt][2 * kc + 1]);
        }
        float4 wi, wf, wg, wo;
        if (HASX) {
            wi = *(const float4*)(wx + 2 * u0);
            wf = *(const float4*)(wx + 2 * (64 + u0));
            wg = *(const float4*)(wx + 2 * (128 + u0));
            wo = *(const float4*)(wx + 2 * (192 + u0));
        }
        float2 f0v, f1v;
        if (FC) {
            f0v = *(const float2*)(fcw + u0);
            f1v = *(const float2*)(fcw + 64 + u0);
        }
        float hv[4];
#pragma unroll
        for (int e = 0; e < 4; e++) {
            const int o = e & 1;
            float gi = d[0][e];
            float gf = d[1][e];
            float gg = d[2][e];
            float go = d[3][e];
            if (HASX) {
                float xa = (e < 2) ? x0l : x0h, xb = (e < 2) ? x1l : x1h;
                gi += xa * (o ? wi.z : wi.x) + xb * (o ? wi.w : wi.y);
                gf += xa * (o ? wf.z : wf.x) + xb * (o ? wf.w : wf.y);
                gg += xa * (o ? wg.z : wg.x) + xb * (o ? wg.w : wg.y);
                go += xa * (o ? wo.z : wo.x) + xb * (o ? wo.w : wo.y);
            }
            // sigma(x)=0.5*tanh(x/2)+0.5, 0.5 prescaled into W/b for i,f,o
            float ti = tanhg(gi), tf_ = tanhg(gf), tg = tanhg(gg), to = tanhg(go);
            float si = fmaf(0.5f, ti, 0.5f);
            float sf = fmaf(0.5f, tf_, 0.5f);
            float so = fmaf(0.5f, to, 0.5f);
            float cc = c[ut * 4 + e];
            cc = fmaf(si, tg, sf * cc);
            c[ut * 4 + e] = cc;
            hv[e] = so * tanhg(cc);
        }
        if (FC) {
            sfc[0] += hv[0] * f0v.x + hv[1] * f0v.y;
            sfc[1] += hv[0] * f1v.x + hv[1] * f1v.y;
            sfc[2] += hv[2] * f0v.x + hv[3] * f0v.y;
            sfc[3] += hv[2] * f1v.x + hv[3] * f1v.y;
        }
        __half2 plo = __floats2half2_rn(hv[0], hv[1]);
        __half2 phi = __floats2half2_rn(hv[2], hv[3]);
        nhl[ut] = *(uint32_t*)&plo;
        nhh[ut] = *(uint32_t*)&phi;
    }
#pragma unroll
    for (int i = 0; i < 8; i++) { hl[i] = nhl[i]; hh[i] = nhh[i]; }
}

__global__ __launch_bounds__(NT, 1)
void SimpleLSTM_49709951484004_kernel(
    const float* __restrict__ obs,
    const float* __restrict__ eWih0, const float* __restrict__ eWhh0,
    const float* __restrict__ eBih0, const float* __restrict__ eBhh0,
    const float* __restrict__ eWih1, const float* __restrict__ eWhh1,
    const float* __restrict__ eBih1, const float* __restrict__ eBhh1,
    const float* __restrict__ dWih0, const float* __restrict__ dWhh0,
    const float* __restrict__ dBih0, const float* __restrict__ dBhh0,
    const float* __restrict__ dWih1, const float* __restrict__ dWhh1,
    const float* __restrict__ dBih1, const float* __restrict__ dBhh1,
    const float* __restrict__ fcW, const float* __restrict__ fcb,
    float* __restrict__ out, int Btot)
{
    extern __shared__ char smraw[];
    Smem* s = (Smem*)smraw;
    const int tid = threadIdx.x;
    const int w = tid >> 5, l = tid & 31, l4 = l >> 2, lm4 = l & 3;
    const int rl = w * 16 + l4;
    const long base = (long)blockIdx.x * ROWS;
    const int j = l & 7, tt = l >> 3;
    const uint32_t lmoff = (uint32_t)(j * 128 + (((tt ^ j) & 7) << 4));

    for (int i = tid; i < ROWS * 16; i += NT)
        s->obs[i] = (base + i / 16 < Btot) ? obs[base * 16 + i] : 0.f;
    loadW(s->W[0], eWhh0); loadW(s->W[1], eWih1); loadW(s->W[2], eWhh1);
    loadW(s->W[3], dWhh0); loadW(s->W[4], dWih1); loadW(s->W[5], dWhh1);
    loadSmall(s->wxe, s->b0e, s->b1e, eWih0, eBih0, eBhh0, eBih1, eBhh1);
    loadSmall(s->wxd, s->b0d, s->b1d, dWih0, dBih0, dBhh0, dBih1, dBhh1);
    if (tid < 128) s->fcw[tid] = fcW[tid];
    if (tid < 2) s->fcb[tid] = fcb[tid];
    __syncthreads();

    const uint32_t uW = smem_u32(s->W[0]);

    uint32_t h0l[8], h0h[8], h1l[8], h1h[8];
    float c0[32], c1[32];
#pragma unroll
    for (int i = 0; i < 8; i++) { h0l[i] = h0h[i] = h1l[i] = h1h[i] = 0u; }
#pragma unroll
    for (int i = 0; i < 32; i++) { c0[i] = 0.f; c1[i] = 0.f; }

    // ---------------- encoder: 8 steps ----------------
#pragma unroll 1
    for (int t = 0; t < 8; t++) {
        float x0l = s->obs[rl * 16 + 2 * t], x1l = s->obs[rl * 16 + 2 * t + 1];
        float x0h = s->obs[(rl + 8) * 16 + 2 * t], x1h = s->obs[(rl + 8) * 16 + 2 * t + 1];
        layer<true, false, false>(uW, 0u, s->b0e, s->wxe, nullptr,
                                  x0l, x1l, x0h, x1h, h0l, h0h, nullptr, nullptr,
                                  c0, nullptr, lm4, lmoff);
        layer<false, true, false>(uW + 2 * 32768u, uW + 1 * 32768u, s->b1e, nullptr,
                                  nullptr, 0.f, 0.f, 0.f, 0.f, h1l, h1h, h0l, h0h,
                                  c1, nullptr, lm4, lmoff);
    }

    // ---------------- decoder: 12 steps ----------------
    float x0l = s->obs[rl * 16 + 14], x1l = s->obs[rl * 16 + 15];
    float x0h = s->obs[(rl + 8) * 16 + 14], x1h = s->obs[(rl + 8) * 16 + 15];
#pragma unroll 1
    for (int t = 0; t < 12; t++) {
        layer<true, false, false>(uW + 3 * 32768u, 0u, s->b0d, s->wxd, nullptr,
                                  x0l, x1l, x0h, x1h, h0l, h0h, nullptr, nullptr,
                                  c0, nullptr, lm4, lmoff);
        float sfc[4] = {0.f, 0.f, 0.f, 0.f};
        layer<false, true, true>(uW + 5 * 32768u, uW + 4 * 32768u, s->b1d, nullptr,
                                 s->fcw, 0.f, 0.f, 0.f, 0.f, h1l, h1h, h0l, h0h,
                                 c1, sfc, lm4, lmoff);
#pragma unroll
        for (int i = 0; i < 4; i++) {
            sfc[i] += __shfl_xor_sync(0xffffffffu, sfc[i], 1);
            sfc[i] += __shfl_xor_sync(0xffffffffu, sfc[i], 2);
        }
        x0l = sfc[0] + s->fcb[0]; x1l = sfc[1] + s->fcb[1];
        x0h = sfc[2] + s->fcb[0]; x1h = sfc[3] + s->fcb[1];
        if (lm4 == 0) {
            long r0 = base + rl, r1 = r0 + 8;
            if (r0 < Btot) { out[r0 * 24 + t * 2] = x0l; out[r0 * 24 + t * 2 + 1] = x1l; }
            if (r1 < Btot) { out[r1 * 24 + t * 2] = x0h; out[r1 * 24 + t * 2 + 1] = x1h; }
        }
    }
}

extern "C" void kernel_launch(void* const* d_in, const int* in_sizes, int n_in,
                              void* d_out, int out_size) {
    int Btot = in_sizes[0] / 16;
    int grid = (Btot + ROWS - 1) / ROWS;
    cudaFuncSetAttribute(SimpleLSTM_49709951484004_kernel,
                         cudaFuncAttributeMaxDynamicSharedMemorySize,
                         (int)sizeof(Smem));
    SimpleLSTM_49709951484004_kernel<<<grid, NT, sizeof(Smem)>>>(
        (const float*)d_in[0], (const float*)d_in[1], (const float*)d_in[2],
        (const float*)d_in[3], (const float*)d_in[4], (const float*)d_in[5],
        (const float*)d_in[6], (const float*)d_in[7], (const float*)d_in[8],
        (const float*)d_in[9], (const float*)d_in[10], (const float*)d_in[11],
        (const float*)d_in[12], (const float*)d_in[13], (const float*)d_in[14],
        (const float*)d_in[15], (const float*)d_in[16], (const float*)d_in[17],
        (const float*)d_in[18], (float*)d_out, Btot);
}

// round 10
// speedup vs baseline: 1.5357x; 1.0773x over previous
#include <cuda_runtime.h>
#include <cuda_fp16.h>
#include <cstdint>

#define NT 256
#define ROWS 128

struct Smem {
    __half W[3][16384];      // phase weights (swizzled, prescaled)
    __half h0[2][8192];      // [buf][row*64 + unit], 128B rows, 16B-chunk swizzle
    __half h1[2][8192];
    float wx[512], b0[256], b1[256];
    float fcw[128], fcb[2];
    float fcpart[8][ROWS][2];
    float pred[ROWS * 2];
    float obs[ROWS * 16];
};

__device__ __forceinline__ float tanhg(float x) {
    float r; asm("tanh.approx.f32 %0, %1;" : "=f"(r) : "f"(x)); return r;
}
__device__ __forceinline__ uint32_t smem_u32(const void* p) {
    uint32_t a;
    asm("{ .reg .u64 t; cvta.to.shared.u64 t, %1; cvt.u32.u64 %0, t; }"
        : "=r"(a) : "l"(p));
    return a;
}
__device__ __forceinline__ void ldm4(uint32_t* f, uint32_t addr) {
    asm volatile("ldmatrix.sync.aligned.m8n8.x4.shared.b16 {%0,%1,%2,%3}, [%4];"
        : "=r"(f[0]), "=r"(f[1]), "=r"(f[2]), "=r"(f[3]) : "r"(addr));
}
__device__ __forceinline__ void mma16(float* d, uint32_t a0, uint32_t a1,
                                      uint32_t a2, uint32_t a3,
                                      uint32_t b0, uint32_t b1) {
    asm volatile(
        "mma.sync.aligned.m16n8k16.row.col.f32.f16.f16.f32 "
        "{%0,%1,%2,%3},{%4,%5,%6,%7},{%8,%9},{%0,%1,%2,%3};"
        : "+f"(d[0]), "+f"(d[1]), "+f"(d[2]), "+f"(d[3])
        : "r"(a0), "r"(a1), "r"(a2), "r"(a3), "r"(b0), "r"(b1));
}

// W[g][k] fp32 global -> fp16 smem, prescaled (0.5 i/f/o, 1.0 g gate);
// 16B chunk c of row g stored at chunk c ^ (g&7).
__device__ __forceinline__ void loadW(__half* Wt, const float* __restrict__ G) {
    for (int i = threadIdx.x; i < 8192; i += NT) {
        int g = i >> 5, w = i & 31;
        float sc = ((g >> 6) == 2) ? 1.0f : 0.5f;
        float2 v = *(const float2*)(G + g * 64 + 2 * w);
        int pos = (w >> 2) ^ (g & 7);
        *(__half2*)(Wt + g * 64 + pos * 8 + (w & 3) * 2) =
            __floats2half2_rn(v.x * sc, v.y * sc);
    }
}
__device__ __forceinline__ void loadSmall(float* wx, float* b0, float* b1,
                                          const float* Wih0,
                                          const float* Bi0, const float* Bh0,
                                          const float* Bi1, const float* Bh1) {
    for (int g = threadIdx.x; g < 256; g += NT) {
        float sc = ((g >> 6) == 2) ? 1.0f : 0.5f;
        wx[2 * g] = Wih0[2 * g] * sc;
        wx[2 * g + 1] = Wih0[2 * g + 1] * sc;
        b0[g] = (Bi0[g] + Bh0[g]) * sc;
        b1[g] = (Bi1[g] + Bh1[g]) * sc;
    }
}
// Load this warp's weight-fragment slice (units w*8..+8 of each gate).
__device__ __forceinline__ void loadFrags(uint32_t (*f)[8], uint32_t mbase,
                                          int w, uint32_t lmoff) {
#pragma unroll
    for (int gt = 0; gt < 4; gt++) {
        uint32_t a0 = mbase + (uint32_t)((gt * 64 + w * 8) * 128) + lmoff;
        ldm4(f[gt], a0);
        ldm4(f[gt] + 4, a0 ^ 64u);
    }
}

// One layer step: gates = hA0 @ fWa^T (+ hA1 @ fWb^T if L1MODE) (+ x@wx if HASX),
// cell update, h -> hout (swizzled). Warp covers units w*8..+8, all 128 rows.
template <bool L1MODE, bool HASX, bool FC>
__device__ __forceinline__ void stepLayer(
    uint32_t hA0, uint32_t hA1, __half* hout,
    const uint32_t (*fWa)[8], const uint32_t (*fWb)[8],
    const float* bias, const float* wx, const float* xb, int xstr,
    const float* fcw, float* fcpart, float* c,
    int w, int l4, int lm4, int arow, int acb, int j)
{
#pragma unroll
    for (int st = 0; st < 8; st++) {
        uint32_t fa0[16], fa1[16];
#pragma unroll
        for (int kc = 0; kc < 4; kc++)
            ldm4(fa0 + 4 * kc,
                 hA0 + st * 2048 + arow * 128 + ((((kc << 1) | acb) ^ j) << 4));
        if (L1MODE)
#pragma unroll
            for (int kc = 0; kc < 4; kc++)
                ldm4(fa1 + 4 * kc,
                     hA1 + st * 2048 + arow * 128 + ((((kc << 1) | acb) ^ j) << 4));
        float d[4][4];
#pragma unroll
        for (int gt = 0; gt < 4; gt++) {
            float2 bb = *(const float2*)(bias + gt * 64 + w * 8 + 2 * lm4);
            d[gt][0] = bb.x; d[gt][1] = bb.y; d[gt][2] = bb.x; d[gt][3] = bb.y;
        }
#pragma unroll
        for (int kc = 0; kc < 4; kc++)
#pragma unroll
            for (int gt = 0; gt < 4; gt++)
                mma16(d[gt], fa0[4 * kc], fa0[4 * kc + 1], fa0[4 * kc + 2],
                      fa0[4 * kc + 3], fWa[gt][2 * kc], fWa[gt][2 * kc + 1]);
        if (L1MODE)
#pragma unroll
            for (int kc = 0; kc < 4; kc++)
#pragma unroll
                for (int gt = 0; gt < 4; gt++)
                    mma16(d[gt], fa1[4 * kc], fa1[4 * kc + 1], fa1[4 * kc + 2],
                          fa1[4 * kc + 3], fWb[gt][2 * kc], fWb[gt][2 * kc + 1]);
        float x0l, x1l, x0h, x1h;
        float4 wi, wf, wg, wo;
        if (HASX) {
            float2 va = *(const float2*)(xb + (st * 16 + l4) * xstr);
            float2 vb = *(const float2*)(xb + (st * 16 + l4 + 8) * xstr);
            x0l = va.x; x1l = va.y; x0h = vb.x; x1h = vb.y;
            wi = *(const float4*)(wx + w * 16 + 4 * lm4);
            wf = *(const float4*)(wx + 128 + w * 16 + 4 * lm4);
            wg = *(const float4*)(wx + 256 + w * 16 + 4 * lm4);
            wo = *(const float4*)(wx + 384 + w * 16 + 4 * lm4);
        }
        float hv[4];
#pragma unroll
        for (int e = 0; e < 4; e++) {
            const int o = e & 1;
            float gi = d[0][e], gf = d[1][e], gg = d[2][e], go = d[3][e];
            if (HASX) {
                float xa = (e < 2) ? x0l : x0h, xv = (e < 2) ? x1l : x1h;
                gi += xa * (o ? wi.z : wi.x) + xv * (o ? wi.w : wi.y);
                gf += xa * (o ? wf.z : wf.x) + xv * (o ? wf.w : wf.y);
                gg += xa * (o ? wg.z : wg.x) + xv * (o ? wg.w : wg.y);
                go += xa * (o ? wo.z : wo.x) + xv * (o ? wo.w : wo.y);
            }
            float ti = tanhg(gi), tf_ = tanhg(gf), tg = tanhg(gg), to = tanhg(go);
            float si = fmaf(0.5f, ti, 0.5f);
            float sf = fmaf(0.5f, tf_, 0.5f);
            float so = fmaf(0.5f, to, 0.5f);
            float cc = c[st * 4 + e];
            cc = fmaf(si, tg, sf * cc);
            c[st * 4 + e] = cc;
            hv[e] = so * tanhg(cc);
        }
        if (FC) {
            float2 f0v = *(const float2*)(fcw + w * 8 + 2 * lm4);
            float2 f1v = *(const float2*)(fcw + 64 + w * 8 + 2 * lm4);
            float sfc[4];
            sfc[0] = hv[0] * f0v.x + hv[1] * f0v.y;
            sfc[1] = hv[0] * f1v.x + hv[1] * f1v.y;
            sfc[2] = hv[2] * f0v.x + hv[3] * f0v.y;
            sfc[3] = hv[2] * f1v.x + hv[3] * f1v.y;
#pragma unroll
            for (int i = 0; i < 4; i++) {
                sfc[i] += __shfl_xor_sync(0xffffffffu, sfc[i], 1);
                sfc[i] += __shfl_xor_sync(0xffffffffu, sfc[i], 2);
            }
            if (lm4 == 0) {
                *(float2*)(fcpart + (st * 16 + l4) * 2) = make_float2(sfc[0], sfc[1]);
                *(float2*)(fcpart + (st * 16 + l4 + 8) * 2) = make_float2(sfc[2], sfc[3]);
            }
        }
        {
            __half2 plo = __floats2half2_rn(hv[0], hv[1]);
            __half2 phi = __floats2half2_rn(hv[2], hv[3]);
            int r0 = st * 16 + l4;
            int co = ((w ^ l4) << 4) + lm4 * 4;   // (r0&7)==l4, ((r0+8)&7)==l4
            *(__half2*)((char*)hout + r0 * 128 + co) = plo;
            *(__half2*)((char*)hout + (r0 + 8) * 128 + co) = phi;
        }
    }
}

__global__ __launch_bounds__(NT, 1)
void SimpleLSTM_49709951484004_kernel(
    const float* __restrict__ obs,
    const float* __restrict__ eWih0, const float* __restrict__ eWhh0,
    const float* __restrict__ eBih0, const float* __restrict__ eBhh0,
    const float* __restrict__ eWih1, const float* __restrict__ eWhh1,
    const float* __restrict__ eBih1, const float* __restrict__ eBhh1,
    const float* __restrict__ dWih0, const float* __restrict__ dWhh0,
    const float* __restrict__ dBih0, const float* __restrict__ dBhh0,
    const float* __restrict__ dWih1, const float* __restrict__ dWhh1,
    const float* __restrict__ dBih1, const float* __restrict__ dBhh1,
    const float* __restrict__ fcW, const float* __restrict__ fcb,
    float* __restrict__ out, int Btot)
{
    extern __shared__ char smraw[];
    Smem* s = (Smem*)smraw;
    const int tid = threadIdx.x;
    const int w = tid >> 5, l = tid & 31, l4 = l >> 2, lm4 = l & 3;
    const int j = l & 7, tt = l >> 3;
    const uint32_t lmoff = (uint32_t)(j * 128 + (((tt ^ j) & 7) << 4)); // B-pattern
    const int arow = (l & 7) + ((l >> 3) & 1) * 8;                      // A-pattern
    const int acb = (l >> 4) & 1;
    const long base = (long)blockIdx.x * ROWS;

    for (int i = tid; i < ROWS * 16; i += NT)
        s->obs[i] = (base + i / 16 < Btot) ? obs[base * 16 + i] : 0.f;
    loadW(s->W[0], eWhh0); loadW(s->W[1], eWih1); loadW(s->W[2], eWhh1);
    loadSmall(s->wx, s->b0, s->b1, eWih0, eBih0, eBhh0, eBih1, eBhh1);
    if (tid < 128) s->fcw[tid] = fcW[tid];
    if (tid < 2) s->fcb[tid] = fcb[tid];
    for (int i = tid; i < 4096; i += NT) {
        ((uint32_t*)s->h0[0])[i] = 0u;
        ((uint32_t*)s->h1[0])[i] = 0u;
    }
    __syncthreads();

    const uint32_t uW = smem_u32(s->W[0]);
    const uint32_t uh0[2] = { smem_u32(s->h0[0]), smem_u32(s->h0[1]) };
    const uint32_t uh1[2] = { smem_u32(s->h1[0]), smem_u32(s->h1[1]) };

    uint32_t fW0[4][8], fW1a[4][8], fW1b[4][8];
    loadFrags(fW0, uW, w, lmoff);
    loadFrags(fW1a, uW + 32768u, w, lmoff);
    loadFrags(fW1b, uW + 65536u, w, lmoff);

    float c0[32], c1[32];
#pragma unroll
    for (int i = 0; i < 32; i++) { c0[i] = 0.f; c1[i] = 0.f; }
    int p0 = 0, p1 = 0;

    // ---------------- encoder: 8 steps ----------------
#pragma unroll 1
    for (int t = 0; t < 8; t++) {
        stepLayer<false, true, false>(uh0[p0], 0u, s->h0[p0 ^ 1], fW0, fW0,
                                      s->b0, s->wx, s->obs + 2 * t, 16,
                                      nullptr, nullptr, c0, w, l4, lm4, arow, acb, j);
        __syncthreads();
        stepLayer<true, false, false>(uh0[p0 ^ 1], uh1[p1], s->h1[p1 ^ 1], fW1a, fW1b,
                                      s->b1, nullptr, nullptr, 0,
                                      nullptr, nullptr, c1, w, l4, lm4, arow, acb, j);
        __syncthreads();
        p0 ^= 1; p1 ^= 1;
    }

    // ---------------- phase switch ----------------
    loadW(s->W[0], dWhh0); loadW(s->W[1], dWih1); loadW(s->W[2], dWhh1);
    loadSmall(s->wx, s->b0, s->b1, dWih0, dBih0, dBhh0, dBih1, dBhh1);
    __syncthreads();
    loadFrags(fW0, uW, w, lmoff);
    loadFrags(fW1a, uW + 32768u, w, lmoff);
    loadFrags(fW1b, uW + 65536u, w, lmoff);

    // ---------------- decoder: 12 steps ----------------
#pragma unroll 1
    for (int t = 0; t < 12; t++) {
        const float* xb = (t == 0) ? (s->obs + 14) : s->pred;
        const int xstr = (t == 0) ? 16 : 2;
        stepLayer<false, true, false>(uh0[p0], 0u, s->h0[p0 ^ 1], fW0, fW0,
                                      s->b0, s->wx, xb, xstr,
                                      nullptr, nullptr, c0, w, l4, lm4, arow, acb, j);
        __syncthreads();
        stepLayer<true, false, true>(uh0[p0 ^ 1], uh1[p1], s->h1[p1 ^ 1], fW1a, fW1b,
                                     s->b1, nullptr, nullptr, 0,
                                     s->fcw, &s->fcpart[w][0][0], c1,
                                     w, l4, lm4, arow, acb, j);
        __syncthreads();
        {
            int row = tid >> 1, o = tid & 1;
            float v = s->fcb[o];
#pragma unroll
            for (int w8 = 0; w8 < 8; w8++) v += s->fcpart[w8][row][o];
            s->pred[row * 2 + o] = v;
            long gr = base + row;
            if (gr < Btot) out[gr * 24 + t * 2 + o] = v;
        }
        __syncthreads();
        p0 ^= 1; p1 ^= 1;
    }
}

extern "C" void kernel_launch(void* const* d_in, const int* in_sizes, int n_in,
                              void* d_out, int out_size) {
    int Btot = in_sizes[0] / 16;
    int grid = (Btot + ROWS - 1) / ROWS;
    cudaFuncSetAttribute(SimpleLSTM_49709951484004_kernel,
                         cudaFuncAttributeMaxDynamicSharedMemorySize,
                         (int)sizeof(Smem));
    SimpleLSTM_49709951484004_kernel<<<grid, NT, sizeof(Smem)>>>(
        (const float*)d_in[0], (const float*)d_in[1], (const float*)d_in[2],
        (const float*)d_in[3], (const float*)d_in[4], (const float*)d_in[5],
        (const float*)d_in[6], (const float*)d_in[7], (const float*)d_in[8],
        (const float*)d_in[9], (const float*)d_in[10], (const float*)d_in[11],
        (const float*)d_in[12], (const float*)d_in[13], (const float*)d_in[14],
        (const float*)d_in[15], (const float*)d_in[16], (const float*)d_in[17],
        (const float*)d_in[18], (float*)d_out, Btot);
}